// round 7
// baseline (speedup 1.0000x reference)
#include <cuda_runtime.h>
#include <math.h>

#define BS 8
#define NP 2048
#define CD 12
#define FD 2
#define DD 24
#define KS 16
#define RPB 8
#define TPB 512
#define MPT 4
#define CAP 128
#define FULLMASK 0xffffffffu

typedef unsigned long long ull;

// smem words: s_q2 (DD*RPB ull) | s_ck (RPB*CAP ull) | s_A (RPB*NP f32) | s_sel
#define SMEM_WORDS (2*DD*RPB + 2*RPB*CAP + RPB*NP + RPB*KS)
#define SMEM_BYTES (SMEM_WORDS * 4)

// normalized features, d-major for coalesced m-loads: gFnT[b][d][m]
__device__ float gFnT[BS][DD][NP];

// ---------------------------------------------------------------------------
// packed f32x2 helpers (Blackwell: fma.rn.f32x2 only reachable via PTX)
// ---------------------------------------------------------------------------
__device__ __forceinline__ ull pack2(float lo, float hi) {
    ull r; asm("mov.b64 %0, {%1, %2};" : "=l"(r) : "f"(lo), "f"(hi)); return r;
}
__device__ __forceinline__ void unpack2(ull v, float& lo, float& hi) {
    asm("mov.b64 {%0, %1}, %2;" : "=f"(lo), "=f"(hi) : "l"(v));
}
__device__ __forceinline__ ull fma2(ull a, ull b, ull c) {
    ull d; asm("fma.rn.f32x2 %0, %1, %2, %3;" : "=l"(d) : "l"(a), "l"(b), "l"(c)); return d;
}

// ---------------------------------------------------------------------------
// prep: normalized features (reference fp32 arithmetic order) + tgt_out copy.
// ---------------------------------------------------------------------------
__global__ void prep_kernel(const float* __restrict__ x, const int* __restrict__ flowp,
                            float* __restrict__ out) {
    int idx = blockIdx.x * blockDim.x + threadIdx.x;
    if (idx >= BS * NP) return;
    int b = idx >> 11;
    int n = idx & (NP - 1);
    int flow = flowp ? flowp[0] : 0;
    const float* xb = x + (size_t)b * (CD * FD * NP);

    float feats[DD];
#pragma unroll
    for (int f = 0; f < FD; f++)
#pragma unroll
        for (int c = 0; c < CD; c++)
            feats[f * CD + c] = xb[(c * FD + f) * NP + n];

    float ss = 0.f;
#pragma unroll
    for (int d = 0; d < DD; d++) ss = __fadd_rn(ss, __fmul_rn(feats[d], feats[d]));
    float denom = __fadd_rn(sqrtf(ss), 1e-8f);
#pragma unroll
    for (int d = 0; d < DD; d++)
        gFnT[b][d][n] = __fdiv_rn(feats[d], denom);

    float* out2 = out + (size_t)BS * NP * KS * CD;
#pragma unroll
    for (int c = 0; c < CD; c++)
        out2[(b * CD + c) * NP + n] = xb[(c * FD + flow) * NP + n];
}

// orderable 64-bit key: (monotone float map) desc, then index asc
__device__ __forceinline__ ull make_key(float v, int idx) {
    unsigned u = __float_as_uint(v);
    u = (u & 0x80000000u) ? ~u : (u | 0x80000000u);
    return ((ull)u << 32) | (unsigned)(NP - 1 - idx);
}
__device__ __forceinline__ int key_idx(ull k) {
    return NP - 1 - (int)(k & 0xffffffffu);
}

// full bitonic sort of 32 keys, descending (lane 0 = largest)
__device__ __forceinline__ ull sort32_desc(ull v, int lane) {
#pragma unroll
    for (int k2 = 2; k2 <= 32; k2 <<= 1) {
#pragma unroll
        for (int j2 = k2 >> 1; j2 > 0; j2 >>= 1) {
            ull o = __shfl_xor_sync(FULLMASK, v, j2);
            bool up = ((lane & k2) == 0);
            bool low = ((lane & j2) == 0);
            ull mx = v > o ? v : o, mn = v > o ? o : v;
            v = (up == low) ? mx : mn;
        }
    }
    return v;
}

// merge: best (desc-sorted) with ch (desc-sorted) -> top-32 of union, desc
__device__ __forceinline__ ull merge32_desc(ull best, ull ch, int lane) {
    ull o = __shfl_sync(FULLMASK, ch, 31 - lane);
    ull v = best > o ? best : o;
#pragma unroll
    for (int j2 = 16; j2 > 0; j2 >>= 1) {
        ull w = __shfl_xor_sync(FULLMASK, v, j2);
        bool low = ((lane & j2) == 0);
        ull mx = v > w ? v : w, mn = v > w ? w : v;
        v = low ? mx : mn;
    }
    return v;
}

// ---------------------------------------------------------------------------
// main: 512 thr, 8 rows. Phase 1: packed-f32x2 register dots (8 rows x
// 2 pairs / thread). Phase 2: warps 0..7, one row each: float4 threshold +
// compaction to 64-bit keys, bitonic sort -> exact ordered top-16, gather.
// ---------------------------------------------------------------------------
__global__ void __launch_bounds__(TPB, 2) main_kernel(const float* __restrict__ x,
                                                      const int* __restrict__ flowp,
                                                      float* __restrict__ out) {
    extern __shared__ float sm[];
    ull*   s_q2  = (ull*)sm;                         // [DD][RPB] packed (q,q)
    ull*   s_ck  = s_q2 + DD * RPB;                  // [RPB][CAP] candidate keys
    float* s_A   = (float*)(s_ck + RPB * CAP);       // [RPB][NP]
    int*   s_sel = (int*)(s_A + RPB * NP);           // [RPB][KS]

    int blk = blockIdx.x;                  // BS * (NP/RPB) = 2048
    int b   = blk >> 8;
    int n0  = (blk & 255) * RPB;
    int tid = threadIdx.x;
    int wid = tid >> 5, lane = tid & 31;

    if (tid < DD * RPB) {
        int d = tid >> 3, r = tid & 7;
        float v = gFnT[b][d][n0 + r];
        s_q2[tid] = pack2(v, v);
    }
    __syncthreads();

    // ---------------- phase 1: packed dots (m = 4*tid + {0..3}) ----------------
    ull a01[RPB], a23[RPB];
#pragma unroll
    for (int r = 0; r < RPB; r++) { a01[r] = 0ULL; a23[r] = 0ULL; }

#pragma unroll 4
    for (int d = 0; d < DD; d++) {
        float4 fm = reinterpret_cast<const float4*>(&gFnT[b][d][0])[tid];
        ull f01 = pack2(fm.x, fm.y);
        ull f23 = pack2(fm.z, fm.w);
        const ulonglong2* q2 = reinterpret_cast<const ulonglong2*>(s_q2 + d * RPB);
        ulonglong2 qA = q2[0], qB = q2[1], qC = q2[2], qD = q2[3];
        ull qq[RPB] = {qA.x, qA.y, qB.x, qB.y, qC.x, qC.y, qD.x, qD.y};
#pragma unroll
        for (int r = 0; r < RPB; r++) {
            a01[r] = fma2(qq[r], f01, a01[r]);
            a23[r] = fma2(qq[r], f23, a23[r]);
        }
    }

#pragma unroll
    for (int r = 0; r < RPB; r++) {
        float4 v;
        unpack2(a01[r], v.x, v.y);
        unpack2(a23[r], v.z, v.w);
        reinterpret_cast<float4*>(s_A + r * NP)[tid] = v;
    }
    __syncthreads();

    // ---------------- phase 2: warp-per-row ----------------
    if (wid < RPB) {
        int r = wid;
        int n = n0 + r;
        const float4* Ar4 = reinterpret_cast<const float4*>(s_A + r * NP);
        const float*  Ar  = s_A + r * NP;
        ull* ck = s_ck + r * CAP;

        // per-lane max over 16 float4s (64 elements)
        float lmax = -INFINITY;
#pragma unroll
        for (int j = 0; j < NP / 128; j++) {
            float4 v = Ar4[lane + 32 * j];
            lmax = fmaxf(lmax, fmaxf(fmaxf(v.x, v.y), fmaxf(v.z, v.w)));
        }

        // threshold: 16th largest of the 32 lane maxima (bitonic desc).
        // >=16 lanes have an element >= T  =>  all true top-16 are >= T.
        float sv = lmax;
#pragma unroll
        for (int k2 = 2; k2 <= 32; k2 <<= 1) {
#pragma unroll
            for (int j2 = k2 >> 1; j2 > 0; j2 >>= 1) {
                float o = __shfl_xor_sync(FULLMASK, sv, j2);
                bool up = ((lane & k2) == 0);
                bool low = ((lane & j2) == 0);
                float mx = fmaxf(sv, o), mn = fminf(sv, o);
                sv = (up == low) ? mx : mn;
            }
        }
        float T = __shfl_sync(FULLMASK, sv, 15);

        // compaction: survivors stored directly as sortable keys
        int cnt = 0;
#pragma unroll
        for (int j = 0; j < NP / 128; j++) {
            float4 v = Ar4[lane + 32 * j];
            int mbase = 4 * (lane + 32 * j);
            float vc[4] = {v.x, v.y, v.z, v.w};
#pragma unroll
            for (int c = 0; c < 4; c++) {
                bool p = (vc[c] >= T);
                unsigned bal = __ballot_sync(FULLMASK, p);
                if (p) {
                    int pos = cnt + __popc(bal & ((1u << lane) - 1u));
                    if (pos < CAP) ck[pos] = make_key(vc[c], mbase + c);
                }
                cnt += __popc(bal);
            }
        }
        __syncwarp();

        ull best;
        if (cnt <= CAP) {
            ull k0 = (lane < cnt) ? ck[lane] : 0ULL;
            best = sort32_desc(k0, lane);
            for (int c0 = 32; c0 < cnt; c0 += 32) {
                int i = c0 + lane;
                ull kc = (i < cnt) ? ck[i] : 0ULL;
                kc = sort32_desc(kc, lane);
                best = merge32_desc(best, kc, lane);
            }
        } else {
            // cold exact fallback: chunk-merge over the full row
            ull k0 = make_key(Ar[lane], lane);
            best = sort32_desc(k0, lane);
            for (int c0 = 32; c0 < NP; c0 += 32) {
                int i = c0 + lane;
                ull kc = sort32_desc(make_key(Ar[i], i), lane);
                best = merge32_desc(best, kc, lane);
            }
        }

        if (lane < KS) s_sel[r * KS + lane] = key_idx(best);
        __syncwarp();

        // gather: sx_c[b][n][k][c] = x_c[b][c][flow][sel[k]]
        int flow = flowp ? flowp[0] : 0;
        const float* xb = x + (size_t)b * (CD * FD * NP);
        float* o1 = out + (size_t)(b * NP + n) * (KS * CD);
        for (int t = lane; t < KS * CD; t += 32) {
            int k = t / CD;
            int c = t - k * CD;
            int m = s_sel[r * KS + k];
            o1[t] = xb[(c * FD + flow) * NP + m];
        }
    }
}

extern "C" void kernel_launch(void* const* d_in, const int* in_sizes, int n_in,
                              void* d_out, int out_size) {
    const float* x = (const float*)d_in[0];
    const int* flowp = (n_in >= 2) ? (const int*)d_in[1] : nullptr;
    float* out = (float*)d_out;

    prep_kernel<<<(BS * NP + 255) / 256, 256>>>(x, flowp, out);

    cudaFuncSetAttribute(main_kernel, cudaFuncAttributeMaxDynamicSharedMemorySize, SMEM_BYTES);
    main_kernel<<<BS * (NP / RPB), TPB, SMEM_BYTES>>>(x, flowp, out);
}

// round 8
// speedup vs baseline: 1.7212x; 1.7212x over previous
#include <cuda_runtime.h>
#include <math.h>

#define BS 8
#define NP 2048
#define CD 12
#define FD 2
#define DD 24
#define KS 16
#define RPB 8
#define TPB 512
#define MPT 4
#define CAP 128
#define FULLMASK 0xffffffffu

typedef unsigned long long ull;

// smem words: s_ck (RPB*CAP ull) | s_q | s_A | s_T | s_cnt | s_sel
#define SMEM_WORDS (2*RPB*CAP + DD*RPB + RPB*NP + 2*RPB + RPB + RPB*KS)
#define SMEM_BYTES (SMEM_WORDS * 4)

// normalized features, d-major for coalesced m-loads: gFnT[b][d][m]
__device__ float gFnT[BS][DD][NP];

// ---------------------------------------------------------------------------
// prep: normalized features (reference fp32 arithmetic order) + tgt_out copy.
// ---------------------------------------------------------------------------
__global__ void prep_kernel(const float* __restrict__ x, const int* __restrict__ flowp,
                            float* __restrict__ out) {
    int idx = blockIdx.x * blockDim.x + threadIdx.x;
    if (idx >= BS * NP) return;
    int b = idx >> 11;
    int n = idx & (NP - 1);
    int flow = flowp ? flowp[0] : 0;
    const float* xb = x + (size_t)b * (CD * FD * NP);

    float feats[DD];
#pragma unroll
    for (int f = 0; f < FD; f++)
#pragma unroll
        for (int c = 0; c < CD; c++)
            feats[f * CD + c] = xb[(c * FD + f) * NP + n];

    float ss = 0.f;
#pragma unroll
    for (int d = 0; d < DD; d++) ss = __fadd_rn(ss, __fmul_rn(feats[d], feats[d]));
    float denom = __fadd_rn(sqrtf(ss), 1e-8f);
#pragma unroll
    for (int d = 0; d < DD; d++)
        gFnT[b][d][n] = __fdiv_rn(feats[d], denom);

    float* out2 = out + (size_t)BS * NP * KS * CD;
#pragma unroll
    for (int c = 0; c < CD; c++)
        out2[(b * CD + c) * NP + n] = xb[(c * FD + flow) * NP + n];
}

// orderable 64-bit key: (monotone float map) desc, then index asc
__device__ __forceinline__ ull make_key(float v, int idx) {
    unsigned u = __float_as_uint(v);
    u = (u & 0x80000000u) ? ~u : (u | 0x80000000u);
    return ((ull)u << 32) | (unsigned)(NP - 1 - idx);
}
__device__ __forceinline__ int key_idx(ull k) {
    return NP - 1 - (int)(k & 0xffffffffu);
}

// full bitonic sort of 32 keys, descending (lane 0 = largest)
template <typename T_>
__device__ __forceinline__ T_ sort32_desc(T_ v, int lane) {
#pragma unroll
    for (int k2 = 2; k2 <= 32; k2 <<= 1) {
#pragma unroll
        for (int j2 = k2 >> 1; j2 > 0; j2 >>= 1) {
            T_ o = __shfl_xor_sync(FULLMASK, v, j2);
            bool up = ((lane & k2) == 0);
            bool low = ((lane & j2) == 0);
            T_ mx = v > o ? v : o, mn = v > o ? o : v;
            v = (up == low) ? mx : mn;
        }
    }
    return v;
}

// merge: best (desc-sorted) with ch (desc-sorted) -> top-32 of union, desc
__device__ __forceinline__ ull merge32_desc(ull best, ull ch, int lane) {
    ull o = __shfl_sync(FULLMASK, ch, 31 - lane);
    ull v = best > o ? best : o;
#pragma unroll
    for (int j2 = 16; j2 > 0; j2 >>= 1) {
        ull w = __shfl_xor_sync(FULLMASK, v, j2);
        bool low = ((lane & j2) == 0);
        ull mx = v > w ? v : w, mn = v > w ? w : v;
        v = low ? mx : mn;
    }
    return v;
}

// ---------------------------------------------------------------------------
// main: 512 thr, 8 rows. Phase 1: scalar register dots (R5 form).
// Phase 2: ALL 16 warps: warp w handles half (w>>3) of row (w&7) — lane-max
// + bitonic threshold per half, T = max of halves, register-resident
// compaction via aggregated atomics; then warps 0..7 sort keys for exact
// ordered top-16 and gather.
// ---------------------------------------------------------------------------
__global__ void __launch_bounds__(TPB, 2) main_kernel(const float* __restrict__ x,
                                                      const int* __restrict__ flowp,
                                                      float* __restrict__ out) {
    extern __shared__ float sm[];
    ull*   s_ck  = (ull*)sm;                      // [RPB][CAP] candidate keys
    float* s_q   = (float*)(s_ck + RPB * CAP);    // [DD][RPB]
    float* s_A   = s_q + DD * RPB;                // [RPB][NP]
    float* s_T   = s_A + RPB * NP;                // [RPB][2]
    int*   s_cnt = (int*)(s_T + RPB * 2);         // [RPB]
    int*   s_sel = s_cnt + RPB;                   // [RPB][KS]

    int blk = blockIdx.x;                  // BS * (NP/RPB) = 2048
    int b   = blk >> 8;
    int n0  = (blk & 255) * RPB;
    int tid = threadIdx.x;
    int wid = tid >> 5, lane = tid & 31;

    if (tid < DD * RPB) {
        int d = tid >> 3, r = tid & 7;
        s_q[tid] = gFnT[b][d][n0 + r];
    }
    if (tid < RPB) s_cnt[tid] = 0;
    __syncthreads();

    // ---------------- phase 1: dots (m = 4*tid + j) ----------------
    float acc[RPB][MPT];
#pragma unroll
    for (int r = 0; r < RPB; r++)
#pragma unroll
        for (int j = 0; j < MPT; j++) acc[r][j] = 0.f;

#pragma unroll 6
    for (int d = 0; d < DD; d++) {
        float4 fm = reinterpret_cast<const float4*>(&gFnT[b][d][0])[tid];
        float4 qa = *reinterpret_cast<const float4*>(&s_q[d * 8]);
        float4 qb = *reinterpret_cast<const float4*>(&s_q[d * 8 + 4]);
        float q[RPB] = {qa.x, qa.y, qa.z, qa.w, qb.x, qb.y, qb.z, qb.w};
        float f[MPT] = {fm.x, fm.y, fm.z, fm.w};
#pragma unroll
        for (int r = 0; r < RPB; r++)
#pragma unroll
            for (int j = 0; j < MPT; j++)
                acc[r][j] = fmaf(q[r], f[j], acc[r][j]);
    }

#pragma unroll
    for (int r = 0; r < RPB; r++)
        reinterpret_cast<float4*>(s_A + r * NP)[tid] =
            make_float4(acc[r][0], acc[r][1], acc[r][2], acc[r][3]);
    __syncthreads();

    // ---------------- phase 2a: per-half lane-max + threshold ----------------
    int r = wid & 7, h = wid >> 3;
    const float4* Ar4 = reinterpret_cast<const float4*>(s_A + r * NP);
    int base4 = h * 256 + lane;            // float4 index of this lane's first group

    float4 v[8];
#pragma unroll
    for (int j = 0; j < 8; j++) v[j] = Ar4[base4 + 32 * j];

    float lmax = -INFINITY;
#pragma unroll
    for (int j = 0; j < 8; j++)
        lmax = fmaxf(lmax, fmaxf(fmaxf(v[j].x, v[j].y), fmaxf(v[j].z, v[j].w)));

    float sv = sort32_desc(lmax, lane);
    if (lane == 15) s_T[r * 2 + h] = sv;   // 16th-largest lane-max of this half
    __syncthreads();

    // ---------------- phase 2b: compaction (register-resident values) -------
    {
        float T = fmaxf(s_T[r * 2], s_T[r * 2 + 1]);
        ull* ck = s_ck + r * CAP;
#pragma unroll
        for (int j = 0; j < 8; j++) {
            int mbase = 4 * (base4 + 32 * j);
            float vc[4] = {v[j].x, v[j].y, v[j].z, v[j].w};
#pragma unroll
            for (int c = 0; c < 4; c++) {
                if (vc[c] >= T) {
                    int pos = atomicAdd(&s_cnt[r], 1);   // warp-aggregated
                    if (pos < CAP) ck[pos] = make_key(vc[c], mbase + c);
                }
            }
        }
    }
    __syncthreads();

    // ---------------- phase 2c: warp-per-row exact top-16 + gather ----------
    if (wid < RPB) {
        int n = n0 + r;
        const float* Ar = s_A + r * NP;
        ull* ck = s_ck + r * CAP;
        int cnt = s_cnt[r];

        ull best;
        if (cnt <= CAP) {
            ull k0 = (lane < cnt) ? ck[lane] : 0ULL;
            best = sort32_desc(k0, lane);
            for (int c0 = 32; c0 < cnt; c0 += 32) {
                int i = c0 + lane;
                ull kc = (i < cnt) ? ck[i] : 0ULL;
                kc = sort32_desc(kc, lane);
                best = merge32_desc(best, kc, lane);
            }
        } else {
            // cold exact fallback: chunk-merge over the full row
            ull k0 = make_key(Ar[lane], lane);
            best = sort32_desc(k0, lane);
            for (int c0 = 32; c0 < NP; c0 += 32) {
                int i = c0 + lane;
                ull kc = sort32_desc(make_key(Ar[i], i), lane);
                best = merge32_desc(best, kc, lane);
            }
        }

        if (lane < KS) s_sel[r * KS + lane] = key_idx(best);
        __syncwarp();

        // gather: sx_c[b][n][k][c] = x_c[b][c][flow][sel[k]]
        int flow = flowp ? flowp[0] : 0;
        const float* xb = x + (size_t)b * (CD * FD * NP);
        float* o1 = out + (size_t)(b * NP + n) * (KS * CD);
        for (int t = lane; t < KS * CD; t += 32) {
            int k = t / CD;
            int c = t - k * CD;
            int m = s_sel[r * KS + k];
            o1[t] = xb[(c * FD + flow) * NP + m];
        }
    }
}

extern "C" void kernel_launch(void* const* d_in, const int* in_sizes, int n_in,
                              void* d_out, int out_size) {
    const float* x = (const float*)d_in[0];
    const int* flowp = (n_in >= 2) ? (const int*)d_in[1] : nullptr;
    float* out = (float*)d_out;

    prep_kernel<<<(BS * NP + 255) / 256, 256>>>(x, flowp, out);

    cudaFuncSetAttribute(main_kernel, cudaFuncAttributeMaxDynamicSharedMemorySize, SMEM_BYTES);
    main_kernel<<<BS * (NP / RPB), TPB, SMEM_BYTES>>>(x, flowp, out);
}